// round 3
// baseline (speedup 1.0000x reference)
#include <cuda_runtime.h>
#include <cstddef>

#define BATCH 16
#define NN 128
#define DD 128
#define EE 64
#define HH 256
#define ROWS (BATCH*NN)   // 2048
#define EPSLN 1e-5f

#define GRELU 1
#define GMASK 2

// ---------------- scratch (static device buffers, no allocation) ----------------
__device__ float g_x[ROWS*DD];
__device__ float g_np[ROWS*HH];
__device__ float g_s[ROWS*HH];
__device__ float g_agg[ROWS*HH];
__device__ float g_u1[ROWS*HH];
__device__ float g_u[ROWS*DD];
__device__ float g_cnt[ROWS];

// ---------------- prep: x = nodes * mask ----------------
__global__ void prep_x_kernel(const float* __restrict__ nodes,
                              const int* __restrict__ mask,
                              float* __restrict__ x) {
    int row = blockIdx.x;         // 0..2047
    int d = threadIdx.x;          // 0..127
    float mi = mask[row] ? 1.f : 0.f;
    x[row*DD + d] = nodes[row*DD + d] * mi;
}

// cnt[b*N+i] = mask[b,i] * sum_j mask[b,j]
__global__ void prep_cnt_kernel(const int* __restrict__ mask,
                                float* __restrict__ cnt) {
    int b = blockIdx.x;
    int j = threadIdx.x;          // 0..127
    __shared__ float red[NN];
    float m = mask[b*NN + j] ? 1.f : 0.f;
    red[j] = m;
    __syncthreads();
    for (int s2 = 64; s2 > 0; s2 >>= 1) {
        if (j < s2) red[j] += red[j + s2];
        __syncthreads();
    }
    cnt[b*NN + j] = m * red[0];
}

// ---------------- fused edge GEMM + relu + masked j-reduction ----------------
// s[b,i,h] = m_i * sum_j m_j * relu( np[b,i,h] + b1[h] + sum_e edges[b,i,j,e]*We[e,h] )
// Each thread owns one h-column (w[64] in regs). Edge rows staged 16 at a time in
// smem and consumed via broadcast LDS.128 (float4) -> 1 LDS per 4 FFMA.
__global__ __launch_bounds__(256, 2)
void edge_msg_kernel(const float* __restrict__ edges,
                     const float* __restrict__ We,    // (64,256)
                     const float* __restrict__ b1,    // (256)
                     const float* __restrict__ np,    // (ROWS,256)
                     const int* __restrict__ mask,
                     float* __restrict__ s_out) {
    int row = blockIdx.x;              // b*N + i
    int b = row >> 7;
    int t = threadIdx.x;               // h column, 0..255

    __shared__ __align__(16) float se[16][EE];   // 16 j-rows of 64 edge features
    __shared__ float smj[16];

    float w[EE];
#pragma unroll
    for (int e = 0; e < EE; e++) w[e] = We[e*HH + t];

    float npv = np[(size_t)row*HH + t] + b1[t];
    float acc = 0.f;

    const float* ebase = edges + (size_t)row * NN * EE;
    const int* mrow = mask + b*NN;

    for (int j0 = 0; j0 < NN; j0 += 16) {
        __syncthreads();
        // 16 rows * 64 floats = 1024 floats = 256 float4 -> one float4 per thread
        ((float4*)se)[t] = ((const float4*)(ebase + j0*EE))[t];
        if (t < 16) smj[t] = mrow[j0 + t] ? 1.f : 0.f;
        __syncthreads();
#pragma unroll
        for (int jj = 0; jj < 16; jj++) {
            float m = smj[jj];
            float h0 = npv, h1 = 0.f, h2 = 0.f, h3 = 0.f;
#pragma unroll
            for (int e = 0; e < EE; e += 4) {
                float4 v = *(const float4*)&se[jj][e];
                h0 = fmaf(v.x, w[e + 0], h0);
                h1 = fmaf(v.y, w[e + 1], h1);
                h2 = fmaf(v.z, w[e + 2], h2);
                h3 = fmaf(v.w, w[e + 3], h3);
            }
            acc = fmaf(m, fmaxf((h0 + h1) + (h2 + h3), 0.f), acc);
        }
    }
    float mi = mask[row] ? 1.f : 0.f;
    s_out[(size_t)row*HH + t] = acc * mi;
}

// ---------------- generic tiled fp32 GEMM ----------------
// C(M,N) = epilogue( [A | A2](M,K) @ W(K,N) )
// A supplies cols [0,K1), A2 (if non-null) supplies cols [K1,K).
// epilogue: +bias[n]*(rowscale? rowscale[m]:1); relu; *mask[m]
__global__ __launch_bounds__(256)
void gemm_k(int M, int N, int K, int K1,
            const float* __restrict__ A, int lda,
            const float* __restrict__ A2, int lda2,
            const float* __restrict__ W, int ldw,
            const float* __restrict__ bias,
            const float* __restrict__ rowscale,
            const int* __restrict__ maskrow,
            float* __restrict__ C, int ldc, int flags) {
    __shared__ float As[64][17];
    __shared__ float Ws[16][64];

    int tid = threadIdx.x;
    int bm = blockIdx.y * 64, bn = blockIdx.x * 64;
    int tx = tid & 15, ty = tid >> 4;

    int arow = tid >> 2;            // 0..63
    int acol4 = (tid & 3) * 4;      // 0,4,8,12
    int wrow = tid >> 4;            // 0..15
    int wcol4 = (tid & 15) * 4;

    float acc[4][4];
#pragma unroll
    for (int i = 0; i < 4; i++)
#pragma unroll
        for (int j = 0; j < 4; j++) acc[i][j] = 0.f;

    for (int k0 = 0; k0 < K; k0 += 16) {
        // A tile
        {
            int gm = bm + arow;
            int gk = k0 + acol4;
            float4 v;
            if (A2 != nullptr && gk >= K1)
                v = *(const float4*)(A2 + (size_t)gm*lda2 + (gk - K1));
            else
                v = *(const float4*)(A + (size_t)gm*lda + gk);
            As[arow][acol4 + 0] = v.x;
            As[arow][acol4 + 1] = v.y;
            As[arow][acol4 + 2] = v.z;
            As[arow][acol4 + 3] = v.w;
        }
        // W tile
        {
            float4 wv = *(const float4*)(W + (size_t)(k0 + wrow)*ldw + bn + wcol4);
            *(float4*)&Ws[wrow][wcol4] = wv;
        }
        __syncthreads();
#pragma unroll
        for (int k = 0; k < 16; k++) {
            float a0 = As[ty*4 + 0][k];
            float a1 = As[ty*4 + 1][k];
            float a2 = As[ty*4 + 2][k];
            float a3 = As[ty*4 + 3][k];
            float4 bv = *(const float4*)&Ws[k][tx*4];
            acc[0][0] = fmaf(a0, bv.x, acc[0][0]);
            acc[0][1] = fmaf(a0, bv.y, acc[0][1]);
            acc[0][2] = fmaf(a0, bv.z, acc[0][2]);
            acc[0][3] = fmaf(a0, bv.w, acc[0][3]);
            acc[1][0] = fmaf(a1, bv.x, acc[1][0]);
            acc[1][1] = fmaf(a1, bv.y, acc[1][1]);
            acc[1][2] = fmaf(a1, bv.z, acc[1][2]);
            acc[1][3] = fmaf(a1, bv.w, acc[1][3]);
            acc[2][0] = fmaf(a2, bv.x, acc[2][0]);
            acc[2][1] = fmaf(a2, bv.y, acc[2][1]);
            acc[2][2] = fmaf(a2, bv.z, acc[2][2]);
            acc[2][3] = fmaf(a2, bv.w, acc[2][3]);
            acc[3][0] = fmaf(a3, bv.x, acc[3][0]);
            acc[3][1] = fmaf(a3, bv.y, acc[3][1]);
            acc[3][2] = fmaf(a3, bv.z, acc[3][2]);
            acc[3][3] = fmaf(a3, bv.w, acc[3][3]);
        }
        __syncthreads();
    }

#pragma unroll
    for (int i = 0; i < 4; i++) {
        int gm = bm + ty*4 + i;
        float rs = 1.f;
        if (rowscale != nullptr) rs = rowscale[gm];
        float mf = 1.f;
        if (flags & GMASK) mf = maskrow[gm] ? 1.f : 0.f;
#pragma unroll
        for (int j = 0; j < 4; j++) {
            int gn = bn + tx*4 + j;
            float v = acc[i][j];
            if (bias != nullptr) v += bias[gn] * rs;
            if (flags & GRELU) v = fmaxf(v, 0.f);
            v *= mf;
            C[(size_t)gm*ldc + gn] = v;
        }
    }
}

// ---------------- fused residual + LayerNorm: x = LN(x + u*mi)*g + b, then *mi ----
__global__ void ln_kernel(const float* __restrict__ u,
                          const int* __restrict__ mask,
                          const float* __restrict__ gw,
                          const float* __restrict__ bw,
                          float* __restrict__ x) {
    int warp = threadIdx.x >> 5;
    int lane = threadIdx.x & 31;
    int row = blockIdx.x * 8 + warp;
    float mi = mask[row] ? 1.f : 0.f;

    float v[4];
#pragma unroll
    for (int q = 0; q < 4; q++) {
        int d = lane + q*32;
        v[q] = x[(size_t)row*DD + d] + u[(size_t)row*DD + d] * mi;
    }
    float s = v[0] + v[1] + v[2] + v[3];
#pragma unroll
    for (int o = 16; o > 0; o >>= 1) s += __shfl_xor_sync(0xffffffffu, s, o);
    float mu = s * (1.f / DD);
    float var = 0.f;
#pragma unroll
    for (int q = 0; q < 4; q++) { float d2 = v[q] - mu; var += d2*d2; }
#pragma unroll
    for (int o = 16; o > 0; o >>= 1) var += __shfl_xor_sync(0xffffffffu, var, o);
    float rstd = rsqrtf(var * (1.f / DD) + EPSLN);
#pragma unroll
    for (int q = 0; q < 4; q++) {
        int d = lane + q*32;
        x[(size_t)row*DD + d] = ((v[q] - mu) * rstd * gw[d] + bw[d]) * mi;
    }
}

// ---------------- host launch ----------------
extern "C" void kernel_launch(void* const* d_in, const int* in_sizes, int n_in,
                              void* d_out, int out_size) {
    const float* nodes  = (const float*)d_in[0];
    const float* edges  = (const float*)d_in[1];
    const int*   mask   = (const int*)d_in[2];
    const float* msg_w1 = (const float*)d_in[3];   // (L,192,256)
    const float* msg_b1 = (const float*)d_in[4];   // (L,256)
    const float* msg_w2 = (const float*)d_in[5];   // (L,256,256)
    const float* msg_b2 = (const float*)d_in[6];   // (L,256)
    const float* upd_w1 = (const float*)d_in[7];   // (L,384,256)
    const float* upd_b1 = (const float*)d_in[8];   // (L,256)
    const float* upd_w2 = (const float*)d_in[9];   // (L,256,128)
    const float* upd_b2 = (const float*)d_in[10];  // (L,128)
    const float* ln_g   = (const float*)d_in[11];  // (L,128)
    const float* ln_b   = (const float*)d_in[12];  // (L,128)
    const float* out_w1 = (const float*)d_in[13];  // (128,256)
    const float* out_b1 = (const float*)d_in[14];  // (256)
    const float* out_w2 = (const float*)d_in[15];  // (256,128)
    const float* out_b2 = (const float*)d_in[16];  // (128)
    float* out = (float*)d_out;

    float *x, *np, *s, *agg, *u1, *u, *cnt;
    cudaGetSymbolAddress((void**)&x,   g_x);
    cudaGetSymbolAddress((void**)&np,  g_np);
    cudaGetSymbolAddress((void**)&s,   g_s);
    cudaGetSymbolAddress((void**)&agg, g_agg);
    cudaGetSymbolAddress((void**)&u1,  g_u1);
    cudaGetSymbolAddress((void**)&u,   g_u);
    cudaGetSymbolAddress((void**)&cnt, g_cnt);

    prep_x_kernel<<<ROWS, DD>>>(nodes, mask, x);
    prep_cnt_kernel<<<BATCH, NN>>>(mask, cnt);

    for (int l = 0; l < 3; l++) {
        const float* w1n = msg_w1 + (size_t)l * 192 * HH;          // node part rows 0..127
        const float* w1e = w1n + (size_t)DD * HH;                  // edge part rows 128..191
        const float* b1  = msg_b1 + (size_t)l * HH;
        const float* w2  = msg_w2 + (size_t)l * HH * HH;
        const float* b2  = msg_b2 + (size_t)l * HH;
        const float* uw1 = upd_w1 + (size_t)l * 384 * HH;
        const float* ub1 = upd_b1 + (size_t)l * HH;
        const float* uw2 = upd_w2 + (size_t)l * HH * DD;
        const float* ub2 = upd_b2 + (size_t)l * DD;
        const float* lg  = ln_g + (size_t)l * DD;
        const float* lb  = ln_b + (size_t)l * DD;

        // np = x @ w1n      (2048,256,K=128)
        gemm_k<<<dim3(HH/64, ROWS/64), 256>>>(ROWS, HH, DD, 0,
            x, DD, nullptr, 0, w1n, HH, nullptr, nullptr, nullptr, np, HH, 0);

        // s = masked relu-reduce of (np + edges@w1e + b1)
        edge_msg_kernel<<<ROWS, 256>>>(edges, w1e, b1, np, mask, s);

        // agg = s @ w2 + cnt*b2   (2048,256,K=256)
        gemm_k<<<dim3(HH/64, ROWS/64), 256>>>(ROWS, HH, HH, 0,
            s, HH, nullptr, 0, w2, HH, b2, cnt, nullptr, agg, HH, 0);

        // u1 = relu([x,agg] @ uw1 + ub1)   (2048,256,K=384, split at 128)
        gemm_k<<<dim3(HH/64, ROWS/64), 256>>>(ROWS, HH, DD + HH, DD,
            x, DD, agg, HH, uw1, HH, ub1, nullptr, nullptr, u1, HH, GRELU);

        // u = u1 @ uw2 + ub2   (2048,128,K=256)
        gemm_k<<<dim3(DD/64, ROWS/64), 256>>>(ROWS, DD, HH, 0,
            u1, HH, nullptr, 0, uw2, DD, ub2, nullptr, nullptr, u, DD, 0);

        // x = LN(x + u*mi)*mi
        ln_kernel<<<ROWS/8, 256>>>(u, mask, lg, lb, x);
    }

    // z = relu(x @ out_w1 + out_b1)  -> reuse u1
    gemm_k<<<dim3(HH/64, ROWS/64), 256>>>(ROWS, HH, DD, 0,
        x, DD, nullptr, 0, out_w1, HH, out_b1, nullptr, nullptr, u1, HH, GRELU);

    // out = (z @ out_w2 + out_b2) * mask
    gemm_k<<<dim3(DD/64, ROWS/64), 256>>>(ROWS, DD, HH, 0,
        u1, HH, nullptr, 0, out_w2, DD, out_b2, nullptr, mask, out, DD, GMASK);
}

// round 4
// speedup vs baseline: 2.6889x; 2.6889x over previous
#include <cuda_runtime.h>
#include <cstddef>

#define BATCH 16
#define NN 128
#define DD 128
#define EE 64
#define HH 256
#define ROWS (BATCH*NN)   // 2048
#define EPSLN 1e-5f

#define GRELU 1
#define GMASK 2

// ---------------- scratch (static device buffers, no allocation) ----------------
__device__ float g_x[ROWS*DD];
__device__ float g_np[ROWS*HH];
__device__ float g_s[ROWS*HH];
__device__ float g_agg[ROWS*HH];
__device__ float g_u1[ROWS*HH];
__device__ float g_u[ROWS*DD];
__device__ float g_cnt[ROWS];

// ---------------- helpers ----------------
__device__ __forceinline__ unsigned f2tf(float f) {
    unsigned r;
    asm("cvt.rna.tf32.f32 %0, %1;" : "=r"(r) : "f"(f));
    return r;
}

__device__ __forceinline__ void mma_tf32(float* d,
                                         unsigned a0, unsigned a1, unsigned a2, unsigned a3,
                                         unsigned b0, unsigned b1) {
    asm volatile("mma.sync.aligned.m16n8k8.row.col.f32.tf32.tf32.f32 "
                 "{%0,%1,%2,%3}, {%4,%5,%6,%7}, {%8,%9}, {%0,%1,%2,%3};"
                 : "+f"(d[0]), "+f"(d[1]), "+f"(d[2]), "+f"(d[3])
                 : "r"(a0), "r"(a1), "r"(a2), "r"(a3), "r"(b0), "r"(b1));
}

// ---------------- prep: x = nodes * mask ----------------
__global__ void prep_x_kernel(const float* __restrict__ nodes,
                              const int* __restrict__ mask,
                              float* __restrict__ x) {
    int row = blockIdx.x;         // 0..2047
    int d = threadIdx.x;          // 0..127
    float mi = mask[row] ? 1.f : 0.f;
    x[row*DD + d] = nodes[row*DD + d] * mi;
}

// cnt[b*N+i] = mask[b,i] * sum_j mask[b,j]
__global__ void prep_cnt_kernel(const int* __restrict__ mask,
                                float* __restrict__ cnt) {
    int b = blockIdx.x;
    int j = threadIdx.x;          // 0..127
    __shared__ float red[NN];
    float m = mask[b*NN + j] ? 1.f : 0.f;
    red[j] = m;
    __syncthreads();
    for (int s2 = 64; s2 > 0; s2 >>= 1) {
        if (j < s2) red[j] += red[j + s2];
        __syncthreads();
    }
    cnt[b*NN + j] = m * red[0];
}

// ---------------- tf32 tensor-core edge kernel ----------------
// s[b,i,h] = m_i * sum_j m_j * relu( np[b,i,h] + b1[h] + sum_e E[j,e]*W[e,h] )
// One block per (b,i). 8 warps; warp w owns h in [w*32, w*32+32).
// E tile (128x64) staged in smem as tf32 bits with stride 68 (conflict-free
// fragment loads). W frags preloaded into registers. relu + masked j-reduction
// fused into the MMA epilogue; final cross-lane shfl tree over row groups.
__global__ __launch_bounds__(256, 2)
void edge_msg_tc(const float* __restrict__ edges,
                 const float* __restrict__ We,    // (64,256)
                 const float* __restrict__ b1,    // (256)
                 const float* __restrict__ np,    // (ROWS,256)
                 const int* __restrict__ mask,
                 float* __restrict__ s_out) {
    __shared__ __align__(16) unsigned sE[128 * 68];  // 34816 B, tf32 bits
    __shared__ float smj[NN];

    int row = blockIdx.x;              // b*N + i
    int b = row >> 7;
    int t = threadIdx.x;
    int w = t >> 5;
    int lane = t & 31;
    int hb = w * 32;
    int r = lane >> 2;                 // 0..7  (row group)
    int c = lane & 3;                  // 0..3  (col group)

    // ---- stage E tile (128 j-rows x 64 e) into smem, converting to tf32 ----
    const float4* src = (const float4*)(edges + (size_t)row * NN * EE);
#pragma unroll
    for (int g = t; g < 2048; g += 256) {   // 2048 float4
        float4 v = src[g];
        int rr = g >> 4, c4 = (g & 15) * 4;
        unsigned* d = &sE[rr * 68 + c4];
        d[0] = f2tf(v.x); d[1] = f2tf(v.y); d[2] = f2tf(v.z); d[3] = f2tf(v.w);
    }
    if (t < NN) smj[t] = mask[b*NN + t] ? 1.f : 0.f;

    // ---- preload B fragments: W[64,256] row-major(k,h) ----
    unsigned B0[4][8], B1[4][8];
#pragma unroll
    for (int nt = 0; nt < 4; nt++) {
        int col = hb + nt*8 + r;
#pragma unroll
        for (int k = 0; k < 8; k++) {
            B0[nt][k] = f2tf(We[(k*8 + c)     * HH + col]);
            B1[nt][k] = f2tf(We[(k*8 + c + 4) * HH + col]);
        }
    }

    // ---- npv = np + b1 for this lane's h columns ----
    float npv0[4], npv1[4];
#pragma unroll
    for (int nt = 0; nt < 4; nt++) {
        int h = hb + nt*8 + 2*c;
        npv0[nt] = np[(size_t)row*HH + h]     + b1[h];
        npv1[nt] = np[(size_t)row*HH + h + 1] + b1[h + 1];
    }

    float s0[4] = {0.f, 0.f, 0.f, 0.f};
    float s1[4] = {0.f, 0.f, 0.f, 0.f};

    __syncthreads();

    // ---- main loop: 8 m-tiles of 16 j-rows ----
#pragma unroll 1
    for (int m0 = 0; m0 < 8; m0++) {
        float acc[4][4];
#pragma unroll
        for (int nt = 0; nt < 4; nt++) {
            acc[nt][0] = 0.f; acc[nt][1] = 0.f; acc[nt][2] = 0.f; acc[nt][3] = 0.f;
        }
        int rbase0 = (m0*16 + r) * 68;
        int rbase1 = (m0*16 + r + 8) * 68;
#pragma unroll
        for (int k = 0; k < 8; k++) {
            unsigned a0 = sE[rbase0 + k*8 + c];
            unsigned a1 = sE[rbase1 + k*8 + c];
            unsigned a2 = sE[rbase0 + k*8 + c + 4];
            unsigned a3 = sE[rbase1 + k*8 + c + 4];
#pragma unroll
            for (int nt = 0; nt < 4; nt++)
                mma_tf32(acc[nt], a0, a1, a2, a3, B0[nt][k], B1[nt][k]);
        }
        // epilogue: relu + masked accumulate over this tile's 2 j-rows per lane
        float mj0 = smj[m0*16 + r];
        float mj1 = smj[m0*16 + r + 8];
#pragma unroll
        for (int nt = 0; nt < 4; nt++) {
            s0[nt] += mj0 * fmaxf(acc[nt][0] + npv0[nt], 0.f)
                    + mj1 * fmaxf(acc[nt][2] + npv0[nt], 0.f);
            s1[nt] += mj0 * fmaxf(acc[nt][1] + npv1[nt], 0.f)
                    + mj1 * fmaxf(acc[nt][3] + npv1[nt], 0.f);
        }
    }

    // ---- cross-lane reduce over row groups (lanes differing in bits 2..4) ----
#pragma unroll
    for (int off = 4; off < 32; off <<= 1) {
#pragma unroll
        for (int nt = 0; nt < 4; nt++) {
            s0[nt] += __shfl_xor_sync(0xffffffffu, s0[nt], off);
            s1[nt] += __shfl_xor_sync(0xffffffffu, s1[nt], off);
        }
    }

    float mi = mask[row] ? 1.f : 0.f;
    if (lane < 4) {
#pragma unroll
        for (int nt = 0; nt < 4; nt++) {
            int h = hb + nt*8 + 2*lane;
            s_out[(size_t)row*HH + h]     = mi * s0[nt];
            s_out[(size_t)row*HH + h + 1] = mi * s1[nt];
        }
    }
}

// ---------------- generic tiled fp32 GEMM ----------------
// C(M,N) = epilogue( [A | A2](M,K) @ W(K,N) )
// A supplies cols [0,K1), A2 (if non-null) supplies cols [K1,K).
// epilogue: +bias[n]*(rowscale? rowscale[m]:1); relu; *mask[m]
__global__ __launch_bounds__(256)
void gemm_k(int M, int N, int K, int K1,
            const float* __restrict__ A, int lda,
            const float* __restrict__ A2, int lda2,
            const float* __restrict__ W, int ldw,
            const float* __restrict__ bias,
            const float* __restrict__ rowscale,
            const int* __restrict__ maskrow,
            float* __restrict__ C, int ldc, int flags) {
    __shared__ float As[64][17];
    __shared__ float Ws[16][64];

    int tid = threadIdx.x;
    int bm = blockIdx.y * 64, bn = blockIdx.x * 64;
    int tx = tid & 15, ty = tid >> 4;

    int arow = tid >> 2;            // 0..63
    int acol4 = (tid & 3) * 4;      // 0,4,8,12
    int wrow = tid >> 4;            // 0..15
    int wcol4 = (tid & 15) * 4;

    float acc[4][4];
#pragma unroll
    for (int i = 0; i < 4; i++)
#pragma unroll
        for (int j = 0; j < 4; j++) acc[i][j] = 0.f;

    for (int k0 = 0; k0 < K; k0 += 16) {
        // A tile
        {
            int gm = bm + arow;
            int gk = k0 + acol4;
            float4 v;
            if (A2 != nullptr && gk >= K1)
                v = *(const float4*)(A2 + (size_t)gm*lda2 + (gk - K1));
            else
                v = *(const float4*)(A + (size_t)gm*lda + gk);
            As[arow][acol4 + 0] = v.x;
            As[arow][acol4 + 1] = v.y;
            As[arow][acol4 + 2] = v.z;
            As[arow][acol4 + 3] = v.w;
        }
        // W tile
        {
            float4 wv = *(const float4*)(W + (size_t)(k0 + wrow)*ldw + bn + wcol4);
            *(float4*)&Ws[wrow][wcol4] = wv;
        }
        __syncthreads();
#pragma unroll
        for (int k = 0; k < 16; k++) {
            float a0 = As[ty*4 + 0][k];
            float a1 = As[ty*4 + 1][k];
            float a2 = As[ty*4 + 2][k];
            float a3 = As[ty*4 + 3][k];
            float4 bv = *(const float4*)&Ws[k][tx*4];
            acc[0][0] = fmaf(a0, bv.x, acc[0][0]);
            acc[0][1] = fmaf(a0, bv.y, acc[0][1]);
            acc[0][2] = fmaf(a0, bv.z, acc[0][2]);
            acc[0][3] = fmaf(a0, bv.w, acc[0][3]);
            acc[1][0] = fmaf(a1, bv.x, acc[1][0]);
            acc[1][1] = fmaf(a1, bv.y, acc[1][1]);
            acc[1][2] = fmaf(a1, bv.z, acc[1][2]);
            acc[1][3] = fmaf(a1, bv.w, acc[1][3]);
            acc[2][0] = fmaf(a2, bv.x, acc[2][0]);
            acc[2][1] = fmaf(a2, bv.y, acc[2][1]);
            acc[2][2] = fmaf(a2, bv.z, acc[2][2]);
            acc[2][3] = fmaf(a2, bv.w, acc[2][3]);
            acc[3][0] = fmaf(a3, bv.x, acc[3][0]);
            acc[3][1] = fmaf(a3, bv.y, acc[3][1]);
            acc[3][2] = fmaf(a3, bv.z, acc[3][2]);
            acc[3][3] = fmaf(a3, bv.w, acc[3][3]);
        }
        __syncthreads();
    }

#pragma unroll
    for (int i = 0; i < 4; i++) {
        int gm = bm + ty*4 + i;
        float rs = 1.f;
        if (rowscale != nullptr) rs = rowscale[gm];
        float mf = 1.f;
        if (flags & GMASK) mf = maskrow[gm] ? 1.f : 0.f;
#pragma unroll
        for (int j = 0; j < 4; j++) {
            int gn = bn + tx*4 + j;
            float v = acc[i][j];
            if (bias != nullptr) v += bias[gn] * rs;
            if (flags & GRELU) v = fmaxf(v, 0.f);
            v *= mf;
            C[(size_t)gm*ldc + gn] = v;
        }
    }
}

// ---------------- fused residual + LayerNorm: x = LN(x + u*mi)*g + b, then *mi ----
__global__ void ln_kernel(const float* __restrict__ u,
                          const int* __restrict__ mask,
                          const float* __restrict__ gw,
                          const float* __restrict__ bw,
                          float* __restrict__ x) {
    int warp = threadIdx.x >> 5;
    int lane = threadIdx.x & 31;
    int row = blockIdx.x * 8 + warp;
    float mi = mask[row] ? 1.f : 0.f;

    float v[4];
#pragma unroll
    for (int q = 0; q < 4; q++) {
        int d = lane + q*32;
        v[q] = x[(size_t)row*DD + d] + u[(size_t)row*DD + d] * mi;
    }
    float s = v[0] + v[1] + v[2] + v[3];
#pragma unroll
    for (int o = 16; o > 0; o >>= 1) s += __shfl_xor_sync(0xffffffffu, s, o);
    float mu = s * (1.f / DD);
    float var = 0.f;
#pragma unroll
    for (int q = 0; q < 4; q++) { float d2 = v[q] - mu; var += d2*d2; }
#pragma unroll
    for (int o = 16; o > 0; o >>= 1) var += __shfl_xor_sync(0xffffffffu, var, o);
    float rstd = rsqrtf(var * (1.f / DD) + EPSLN);
#pragma unroll
    for (int q = 0; q < 4; q++) {
        int d = lane + q*32;
        x[(size_t)row*DD + d] = ((v[q] - mu) * rstd * gw[d] + bw[d]) * mi;
    }
}

// ---------------- host launch ----------------
extern "C" void kernel_launch(void* const* d_in, const int* in_sizes, int n_in,
                              void* d_out, int out_size) {
    const float* nodes  = (const float*)d_in[0];
    const float* edges  = (const float*)d_in[1];
    const int*   mask   = (const int*)d_in[2];
    const float* msg_w1 = (const float*)d_in[3];   // (L,192,256)
    const float* msg_b1 = (const float*)d_in[4];   // (L,256)
    const float* msg_w2 = (const float*)d_in[5];   // (L,256,256)
    const float* msg_b2 = (const float*)d_in[6];   // (L,256)
    const float* upd_w1 = (const float*)d_in[7];   // (L,384,256)
    const float* upd_b1 = (const float*)d_in[8];   // (L,256)
    const float* upd_w2 = (const float*)d_in[9];   // (L,256,128)
    const float* upd_b2 = (const float*)d_in[10];  // (L,128)
    const float* ln_g   = (const float*)d_in[11];  // (L,128)
    const float* ln_b   = (const float*)d_in[12];  // (L,128)
    const float* out_w1 = (const float*)d_in[13];  // (128,256)
    const float* out_b1 = (const float*)d_in[14];  // (256)
    const float* out_w2 = (const float*)d_in[15];  // (256,128)
    const float* out_b2 = (const float*)d_in[16];  // (128)
    float* out = (float*)d_out;

    float *x, *np, *s, *agg, *u1, *u, *cnt;
    cudaGetSymbolAddress((void**)&x,   g_x);
    cudaGetSymbolAddress((void**)&np,  g_np);
    cudaGetSymbolAddress((void**)&s,   g_s);
    cudaGetSymbolAddress((void**)&agg, g_agg);
    cudaGetSymbolAddress((void**)&u1,  g_u1);
    cudaGetSymbolAddress((void**)&u,   g_u);
    cudaGetSymbolAddress((void**)&cnt, g_cnt);

    prep_x_kernel<<<ROWS, DD>>>(nodes, mask, x);
    prep_cnt_kernel<<<BATCH, NN>>>(mask, cnt);

    for (int l = 0; l < 3; l++) {
        const float* w1n = msg_w1 + (size_t)l * 192 * HH;          // node part rows 0..127
        const float* w1e = w1n + (size_t)DD * HH;                  // edge part rows 128..191
        const float* b1  = msg_b1 + (size_t)l * HH;
        const float* w2  = msg_w2 + (size_t)l * HH * HH;
        const float* b2  = msg_b2 + (size_t)l * HH;
        const float* uw1 = upd_w1 + (size_t)l * 384 * HH;
        const float* ub1 = upd_b1 + (size_t)l * HH;
        const float* uw2 = upd_w2 + (size_t)l * HH * DD;
        const float* ub2 = upd_b2 + (size_t)l * DD;
        const float* lg  = ln_g + (size_t)l * DD;
        const float* lb  = ln_b + (size_t)l * DD;

        // np = x @ w1n      (2048,256,K=128)
        gemm_k<<<dim3(HH/64, ROWS/64), 256>>>(ROWS, HH, DD, 0,
            x, DD, nullptr, 0, w1n, HH, nullptr, nullptr, nullptr, np, HH, 0);

        // s = masked relu-reduce of (np + edges@w1e + b1)   [tf32 tensor cores]
        edge_msg_tc<<<ROWS, 256>>>(edges, w1e, b1, np, mask, s);

        // agg = s @ w2 + cnt*b2   (2048,256,K=256)
        gemm_k<<<dim3(HH/64, ROWS/64), 256>>>(ROWS, HH, HH, 0,
            s, HH, nullptr, 0, w2, HH, b2, cnt, nullptr, agg, HH, 0);

        // u1 = relu([x,agg] @ uw1 + ub1)   (2048,256,K=384, split at 128)
        gemm_k<<<dim3(HH/64, ROWS/64), 256>>>(ROWS, HH, DD + HH, DD,
            x, DD, agg, HH, uw1, HH, ub1, nullptr, nullptr, u1, HH, GRELU);

        // u = u1 @ uw2 + ub2   (2048,128,K=256)
        gemm_k<<<dim3(DD/64, ROWS/64), 256>>>(ROWS, DD, HH, 0,
            u1, HH, nullptr, 0, uw2, DD, ub2, nullptr, nullptr, u, DD, 0);

        // x = LN(x + u*mi)*mi
        ln_kernel<<<ROWS/8, 256>>>(u, mask, lg, lb, x);
    }

    // z = relu(x @ out_w1 + out_b1)  -> reuse u1
    gemm_k<<<dim3(HH/64, ROWS/64), 256>>>(ROWS, HH, DD, 0,
        x, DD, nullptr, 0, out_w1, HH, out_b1, nullptr, nullptr, u1, HH, GRELU);

    // out = (z @ out_w2 + out_b2) * mask
    gemm_k<<<dim3(DD/64, ROWS/64), 256>>>(ROWS, DD, HH, 0,
        u1, HH, nullptr, 0, out_w2, DD, out_b2, nullptr, mask, out, DD, GMASK);
}

// round 5
// speedup vs baseline: 3.3780x; 1.2563x over previous
#include <cuda_runtime.h>
#include <cstddef>

#define BATCH 16
#define NN 128
#define DD 128
#define EE 64
#define HH 256
#define ROWS (BATCH*NN)   // 2048
#define EPSLN 1e-5f

#define GRELU 1
#define GMASK 2

// ---------------- scratch (static device buffers, no allocation) ----------------
__device__ float g_x[ROWS*DD];
__device__ float g_np[ROWS*HH];
__device__ float g_s[ROWS*HH];
__device__ float g_agg[ROWS*HH];
__device__ float g_u1[ROWS*HH];
__device__ float g_u[ROWS*DD];
__device__ float g_cnt[ROWS];

// ---------------- helpers ----------------
__device__ __forceinline__ unsigned f2tf(float f) {
    unsigned r;
    asm("cvt.rna.tf32.f32 %0, %1;" : "=r"(r) : "f"(f));
    return r;
}

__device__ __forceinline__ void mma_tf32(float* d,
                                         unsigned a0, unsigned a1, unsigned a2, unsigned a3,
                                         unsigned b0, unsigned b1) {
    asm volatile("mma.sync.aligned.m16n8k8.row.col.f32.tf32.tf32.f32 "
                 "{%0,%1,%2,%3}, {%4,%5,%6,%7}, {%8,%9}, {%0,%1,%2,%3};"
                 : "+f"(d[0]), "+f"(d[1]), "+f"(d[2]), "+f"(d[3])
                 : "r"(a0), "r"(a1), "r"(a2), "r"(a3), "r"(b0), "r"(b1));
}

// ---------------- prep: x = nodes * mask ----------------
__global__ void prep_x_kernel(const float* __restrict__ nodes,
                              const int* __restrict__ mask,
                              float* __restrict__ x) {
    int row = blockIdx.x;         // 0..2047
    int d = threadIdx.x;          // 0..127
    float mi = mask[row] ? 1.f : 0.f;
    x[row*DD + d] = nodes[row*DD + d] * mi;
}

// cnt[b*N+i] = mask[b,i] * sum_j mask[b,j]
__global__ void prep_cnt_kernel(const int* __restrict__ mask,
                                float* __restrict__ cnt) {
    int b = blockIdx.x;
    int j = threadIdx.x;          // 0..127
    __shared__ float red[NN];
    float m = mask[b*NN + j] ? 1.f : 0.f;
    red[j] = m;
    __syncthreads();
    for (int s2 = 64; s2 > 0; s2 >>= 1) {
        if (j < s2) red[j] += red[j + s2];
        __syncthreads();
    }
    cnt[b*NN + j] = m * red[0];
}

// ---------------- tf32 tensor-core edge kernel ----------------
// s[b,i,h] = m_i * sum_j m_j * relu( np[b,i,h] + b1[h] + sum_e E[j,e]*W[e,h] )
__global__ __launch_bounds__(256, 2)
void edge_msg_tc(const float* __restrict__ edges,
                 const float* __restrict__ We,    // (64,256)
                 const float* __restrict__ b1,    // (256)
                 const float* __restrict__ np,    // (ROWS,256)
                 const int* __restrict__ mask,
                 float* __restrict__ s_out) {
    __shared__ __align__(16) unsigned sE[128 * 68];  // 34816 B, tf32 bits
    __shared__ float smj[NN];

    int row = blockIdx.x;              // b*N + i
    int b = row >> 7;
    int t = threadIdx.x;
    int w = t >> 5;
    int lane = t & 31;
    int hb = w * 32;
    int r = lane >> 2;                 // 0..7  (row group)
    int c = lane & 3;                  // 0..3  (col group)

    // ---- stage E tile (128 j-rows x 64 e) into smem, converting to tf32 ----
    const float4* src = (const float4*)(edges + (size_t)row * NN * EE);
#pragma unroll
    for (int g = t; g < 2048; g += 256) {   // 2048 float4
        float4 v = src[g];
        int rr = g >> 4, c4 = (g & 15) * 4;
        unsigned* d = &sE[rr * 68 + c4];
        d[0] = f2tf(v.x); d[1] = f2tf(v.y); d[2] = f2tf(v.z); d[3] = f2tf(v.w);
    }
    if (t < NN) smj[t] = mask[b*NN + t] ? 1.f : 0.f;

    // ---- preload B fragments: W[64,256] row-major(k,h) ----
    unsigned B0[4][8], B1[4][8];
#pragma unroll
    for (int nt = 0; nt < 4; nt++) {
        int col = hb + nt*8 + r;
#pragma unroll
        for (int k = 0; k < 8; k++) {
            B0[nt][k] = f2tf(We[(k*8 + c)     * HH + col]);
            B1[nt][k] = f2tf(We[(k*8 + c + 4) * HH + col]);
        }
    }

    // ---- npv = np + b1 for this lane's h columns ----
    float npv0[4], npv1[4];
#pragma unroll
    for (int nt = 0; nt < 4; nt++) {
        int h = hb + nt*8 + 2*c;
        npv0[nt] = np[(size_t)row*HH + h]     + b1[h];
        npv1[nt] = np[(size_t)row*HH + h + 1] + b1[h + 1];
    }

    float s0[4] = {0.f, 0.f, 0.f, 0.f};
    float s1[4] = {0.f, 0.f, 0.f, 0.f};

    __syncthreads();

    // ---- main loop: 8 m-tiles of 16 j-rows ----
#pragma unroll 1
    for (int m0 = 0; m0 < 8; m0++) {
        float acc[4][4];
#pragma unroll
        for (int nt = 0; nt < 4; nt++) {
            acc[nt][0] = 0.f; acc[nt][1] = 0.f; acc[nt][2] = 0.f; acc[nt][3] = 0.f;
        }
        int rbase0 = (m0*16 + r) * 68;
        int rbase1 = (m0*16 + r + 8) * 68;
#pragma unroll
        for (int k = 0; k < 8; k++) {
            unsigned a0 = sE[rbase0 + k*8 + c];
            unsigned a1 = sE[rbase1 + k*8 + c];
            unsigned a2 = sE[rbase0 + k*8 + c + 4];
            unsigned a3 = sE[rbase1 + k*8 + c + 4];
#pragma unroll
            for (int nt = 0; nt < 4; nt++)
                mma_tf32(acc[nt], a0, a1, a2, a3, B0[nt][k], B1[nt][k]);
        }
        float mj0 = smj[m0*16 + r];
        float mj1 = smj[m0*16 + r + 8];
#pragma unroll
        for (int nt = 0; nt < 4; nt++) {
            s0[nt] += mj0 * fmaxf(acc[nt][0] + npv0[nt], 0.f)
                    + mj1 * fmaxf(acc[nt][2] + npv0[nt], 0.f);
            s1[nt] += mj0 * fmaxf(acc[nt][1] + npv1[nt], 0.f)
                    + mj1 * fmaxf(acc[nt][3] + npv1[nt], 0.f);
        }
    }

    // ---- cross-lane reduce over row groups ----
#pragma unroll
    for (int off = 4; off < 32; off <<= 1) {
#pragma unroll
        for (int nt = 0; nt < 4; nt++) {
            s0[nt] += __shfl_xor_sync(0xffffffffu, s0[nt], off);
            s1[nt] += __shfl_xor_sync(0xffffffffu, s1[nt], off);
        }
    }

    float mi = mask[row] ? 1.f : 0.f;
    if (lane < 4) {
#pragma unroll
        for (int nt = 0; nt < 4; nt++) {
            int h = hb + nt*8 + 2*lane;
            s_out[(size_t)row*HH + h]     = mi * s0[nt];
            s_out[(size_t)row*HH + h + 1] = mi * s1[nt];
        }
    }
}

// ---------------- tf32 tensor-core GEMM ----------------
// C(M,N) = epilogue( [A | A2](M,K) @ W(K,N) )
// Block tile 64x64, 128 threads = 4 warps (2x2), warp tile 32x32, K-chunk 32.
// Requires M%64==0, N%64==0, K%32==0, K1%32==0.
__global__ __launch_bounds__(128)
void gemm_tc(int M, int N, int K, int K1,
             const float* __restrict__ A, int lda,
             const float* __restrict__ A2, int lda2,
             const float* __restrict__ W, int ldw,
             const float* __restrict__ bias,
             const float* __restrict__ rowscale,
             const int* __restrict__ maskrow,
             float* __restrict__ C, int ldc, int flags) {
    __shared__ __align__(16) unsigned sA[64 * 36];   // 64 rows x 32 k, stride 36
    __shared__ __align__(16) unsigned sB[32 * 72];   // 32 k x 64 n,  stride 72

    int tid = threadIdx.x;
    int w = tid >> 5;
    int lane = tid & 31;
    int wm = w & 1, wn = w >> 1;       // 2x2 warp grid
    int r = lane >> 2, c = lane & 3;

    int bm = blockIdx.y * 64, bn = blockIdx.x * 64;

    float acc[2][4][4];
#pragma unroll
    for (int mt = 0; mt < 2; mt++)
#pragma unroll
        for (int nt = 0; nt < 4; nt++)
#pragma unroll
            for (int i = 0; i < 4; i++) acc[mt][nt][i] = 0.f;

    for (int k0 = 0; k0 < K; k0 += 32) {
        // stage A chunk: 64x32 floats = 512 float4, 128 threads -> 4 each
#pragma unroll
        for (int g = tid; g < 512; g += 128) {
            int row = g >> 3, col4 = (g & 7) * 4;
            int gm = bm + row, gk = k0 + col4;
            float4 v;
            if (A2 != nullptr && gk >= K1)
                v = *(const float4*)(A2 + (size_t)gm*lda2 + (gk - K1));
            else
                v = *(const float4*)(A + (size_t)gm*lda + gk);
            unsigned* d = &sA[row*36 + col4];
            d[0] = f2tf(v.x); d[1] = f2tf(v.y); d[2] = f2tf(v.z); d[3] = f2tf(v.w);
        }
        // stage B chunk: 32x64 floats = 512 float4
#pragma unroll
        for (int g = tid; g < 512; g += 128) {
            int row = g >> 4, col4 = (g & 15) * 4;
            float4 v = *(const float4*)(W + (size_t)(k0 + row)*ldw + bn + col4);
            unsigned* d = &sB[row*72 + col4];
            d[0] = f2tf(v.x); d[1] = f2tf(v.y); d[2] = f2tf(v.z); d[3] = f2tf(v.w);
        }
        __syncthreads();
#pragma unroll
        for (int kk = 0; kk < 4; kk++) {
            unsigned b0[4], b1[4];
#pragma unroll
            for (int nt = 0; nt < 4; nt++) {
                int col = wn*32 + nt*8 + r;
                b0[nt] = sB[(kk*8 + c)     * 72 + col];
                b1[nt] = sB[(kk*8 + c + 4) * 72 + col];
            }
#pragma unroll
            for (int mt = 0; mt < 2; mt++) {
                int row0 = (wm*32 + mt*16 + r) * 36;
                int row1 = (wm*32 + mt*16 + r + 8) * 36;
                unsigned a0 = sA[row0 + kk*8 + c];
                unsigned a1 = sA[row1 + kk*8 + c];
                unsigned a2 = sA[row0 + kk*8 + c + 4];
                unsigned a3 = sA[row1 + kk*8 + c + 4];
#pragma unroll
                for (int nt = 0; nt < 4; nt++)
                    mma_tf32(acc[mt][nt], a0, a1, a2, a3, b0[nt], b1[nt]);
            }
        }
        __syncthreads();
    }

    // epilogue
#pragma unroll
    for (int mt = 0; mt < 2; mt++) {
#pragma unroll
        for (int i2 = 0; i2 < 2; i2++) {      // row sub (r / r+8)
            int gm = bm + wm*32 + mt*16 + r + i2*8;
            float rs = (rowscale != nullptr) ? rowscale[gm] : 1.f;
            float mf = (flags & GMASK) ? (maskrow[gm] ? 1.f : 0.f) : 1.f;
#pragma unroll
            for (int nt = 0; nt < 4; nt++) {
#pragma unroll
                for (int j = 0; j < 2; j++) {
                    int gn = bn + wn*32 + nt*8 + 2*c + j;
                    float v = acc[mt][nt][i2*2 + j];
                    if (bias != nullptr) v += bias[gn] * rs;
                    if (flags & GRELU) v = fmaxf(v, 0.f);
                    v *= mf;
                    C[(size_t)gm*ldc + gn] = v;
                }
            }
        }
    }
}

// ---------------- fused residual + LayerNorm: x = LN(x + u*mi)*g + b, then *mi ----
__global__ void ln_kernel(const float* __restrict__ u,
                          const int* __restrict__ mask,
                          const float* __restrict__ gw,
                          const float* __restrict__ bw,
                          float* __restrict__ x) {
    int warp = threadIdx.x >> 5;
    int lane = threadIdx.x & 31;
    int row = blockIdx.x * 8 + warp;
    float mi = mask[row] ? 1.f : 0.f;

    float v[4];
#pragma unroll
    for (int q = 0; q < 4; q++) {
        int d = lane + q*32;
        v[q] = x[(size_t)row*DD + d] + u[(size_t)row*DD + d] * mi;
    }
    float s = v[0] + v[1] + v[2] + v[3];
#pragma unroll
    for (int o = 16; o > 0; o >>= 1) s += __shfl_xor_sync(0xffffffffu, s, o);
    float mu = s * (1.f / DD);
    float var = 0.f;
#pragma unroll
    for (int q = 0; q < 4; q++) { float d2 = v[q] - mu; var += d2*d2; }
#pragma unroll
    for (int o = 16; o > 0; o >>= 1) var += __shfl_xor_sync(0xffffffffu, var, o);
    float rstd = rsqrtf(var * (1.f / DD) + EPSLN);
#pragma unroll
    for (int q = 0; q < 4; q++) {
        int d = lane + q*32;
        x[(size_t)row*DD + d] = ((v[q] - mu) * rstd * gw[d] + bw[d]) * mi;
    }
}

// ---------------- host launch ----------------
extern "C" void kernel_launch(void* const* d_in, const int* in_sizes, int n_in,
                              void* d_out, int out_size) {
    const float* nodes  = (const float*)d_in[0];
    const float* edges  = (const float*)d_in[1];
    const int*   mask   = (const int*)d_in[2];
    const float* msg_w1 = (const float*)d_in[3];   // (L,192,256)
    const float* msg_b1 = (const float*)d_in[4];   // (L,256)
    const float* msg_w2 = (const float*)d_in[5];   // (L,256,256)
    const float* msg_b2 = (const float*)d_in[6];   // (L,256)
    const float* upd_w1 = (const float*)d_in[7];   // (L,384,256)
    const float* upd_b1 = (const float*)d_in[8];   // (L,256)
    const float* upd_w2 = (const float*)d_in[9];   // (L,256,128)
    const float* upd_b2 = (const float*)d_in[10];  // (L,128)
    const float* ln_g   = (const float*)d_in[11];  // (L,128)
    const float* ln_b   = (const float*)d_in[12];  // (L,128)
    const float* out_w1 = (const float*)d_in[13];  // (128,256)
    const float* out_b1 = (const float*)d_in[14];  // (256)
    const float* out_w2 = (const float*)d_in[15];  // (256,128)
    const float* out_b2 = (const float*)d_in[16];  // (128)
    float* out = (float*)d_out;

    float *x, *np, *s, *agg, *u1, *u, *cnt;
    cudaGetSymbolAddress((void**)&x,   g_x);
    cudaGetSymbolAddress((void**)&np,  g_np);
    cudaGetSymbolAddress((void**)&s,   g_s);
    cudaGetSymbolAddress((void**)&agg, g_agg);
    cudaGetSymbolAddress((void**)&u1,  g_u1);
    cudaGetSymbolAddress((void**)&u,   g_u);
    cudaGetSymbolAddress((void**)&cnt, g_cnt);

    prep_x_kernel<<<ROWS, DD>>>(nodes, mask, x);
    prep_cnt_kernel<<<BATCH, NN>>>(mask, cnt);

    for (int l = 0; l < 3; l++) {
        const float* w1n = msg_w1 + (size_t)l * 192 * HH;          // node part rows 0..127
        const float* w1e = w1n + (size_t)DD * HH;                  // edge part rows 128..191
        const float* b1  = msg_b1 + (size_t)l * HH;
        const float* w2  = msg_w2 + (size_t)l * HH * HH;
        const float* b2  = msg_b2 + (size_t)l * HH;
        const float* uw1 = upd_w1 + (size_t)l * 384 * HH;
        const float* ub1 = upd_b1 + (size_t)l * HH;
        const float* uw2 = upd_w2 + (size_t)l * HH * DD;
        const float* ub2 = upd_b2 + (size_t)l * DD;
        const float* lg  = ln_g + (size_t)l * DD;
        const float* lb  = ln_b + (size_t)l * DD;

        // np = x @ w1n      (2048,256,K=128)
        gemm_tc<<<dim3(HH/64, ROWS/64), 128>>>(ROWS, HH, DD, 0,
            x, DD, nullptr, 0, w1n, HH, nullptr, nullptr, nullptr, np, HH, 0);

        // s = masked relu-reduce of (np + edges@w1e + b1)   [tf32 tensor cores]
        edge_msg_tc<<<ROWS, 256>>>(edges, w1e, b1, np, mask, s);

        // agg = s @ w2 + cnt*b2   (2048,256,K=256)
        gemm_tc<<<dim3(HH/64, ROWS/64), 128>>>(ROWS, HH, HH, 0,
            s, HH, nullptr, 0, w2, HH, b2, cnt, nullptr, agg, HH, 0);

        // u1 = relu([x,agg] @ uw1 + ub1)   (2048,256,K=384, split at 128)
        gemm_tc<<<dim3(HH/64, ROWS/64), 128>>>(ROWS, HH, DD + HH, DD,
            x, DD, agg, HH, uw1, HH, ub1, nullptr, nullptr, u1, HH, GRELU);

        // u = u1 @ uw2 + ub2   (2048,128,K=256)
        gemm_tc<<<dim3(DD/64, ROWS/64), 128>>>(ROWS, DD, HH, 0,
            u1, HH, nullptr, 0, uw2, DD, ub2, nullptr, nullptr, u, DD, 0);

        // x = LN(x + u*mi)*mi
        ln_kernel<<<ROWS/8, 256>>>(u, mask, lg, lb, x);
    }

    // z = relu(x @ out_w1 + out_b1)  -> reuse u1
    gemm_tc<<<dim3(HH/64, ROWS/64), 128>>>(ROWS, HH, DD, 0,
        x, DD, nullptr, 0, out_w1, HH, out_b1, nullptr, nullptr, u1, HH, GRELU);

    // out = (z @ out_w2 + out_b2) * mask
    gemm_tc<<<dim3(DD/64, ROWS/64), 128>>>(ROWS, DD, HH, 0,
        u1, HH, nullptr, 0, out_w2, DD, out_b2, nullptr, mask, out, DD, GMASK);
}

// round 6
// speedup vs baseline: 3.4871x; 1.0323x over previous
#include <cuda_runtime.h>
#include <cstddef>

#define BATCH 16
#define NN 128
#define DD 128
#define EE 64
#define HH 256
#define ROWS (BATCH*NN)   // 2048
#define EPSLN 1e-5f

#define GRELU 1
#define GMASK 2

// ---------------- scratch (static device buffers, no allocation) ----------------
__device__ float g_x[ROWS*DD];
__device__ float g_np[ROWS*HH];
__device__ float g_s[ROWS*HH];
__device__ float g_agg[ROWS*HH];
__device__ float g_u1[ROWS*HH];
__device__ float g_u[ROWS*DD];
__device__ float g_cnt[ROWS];

// ---------------- helpers ----------------
__device__ __forceinline__ unsigned f2tf(float f) {
    unsigned r;
    asm("cvt.rna.tf32.f32 %0, %1;" : "=r"(r) : "f"(f));
    return r;
}

// hi/lo split: hi = tf32(v), lo = tf32(v - hi)   (3xTF32 scheme)
__device__ __forceinline__ void tfsplit(float v, unsigned& hi, unsigned& lo) {
    hi = f2tf(v);
    lo = f2tf(v - __uint_as_float(hi));
}

__device__ __forceinline__ void mma_tf32(float* d,
                                         unsigned a0, unsigned a1, unsigned a2, unsigned a3,
                                         unsigned b0, unsigned b1) {
    asm volatile("mma.sync.aligned.m16n8k8.row.col.f32.tf32.tf32.f32 "
                 "{%0,%1,%2,%3}, {%4,%5,%6,%7}, {%8,%9}, {%0,%1,%2,%3};"
                 : "+f"(d[0]), "+f"(d[1]), "+f"(d[2]), "+f"(d[3])
                 : "r"(a0), "r"(a1), "r"(a2), "r"(a3), "r"(b0), "r"(b1));
}

// ---------------- prep: x = nodes * mask ----------------
__global__ void prep_x_kernel(const float* __restrict__ nodes,
                              const int* __restrict__ mask,
                              float* __restrict__ x) {
    int row = blockIdx.x;         // 0..2047
    int d = threadIdx.x;          // 0..127
    float mi = mask[row] ? 1.f : 0.f;
    x[row*DD + d] = nodes[row*DD + d] * mi;
}

// cnt[b*N+i] = mask[b,i] * sum_j mask[b,j]
__global__ void prep_cnt_kernel(const int* __restrict__ mask,
                                float* __restrict__ cnt) {
    int b = blockIdx.x;
    int j = threadIdx.x;          // 0..127
    __shared__ float red[NN];
    float m = mask[b*NN + j] ? 1.f : 0.f;
    red[j] = m;
    __syncthreads();
    for (int s2 = 64; s2 > 0; s2 >>= 1) {
        if (j < s2) red[j] += red[j + s2];
        __syncthreads();
    }
    cnt[b*NN + j] = m * red[0];
}

// ---------------- tf32 tensor-core edge kernel ----------------
// s[b,i,h] = m_i * sum_j m_j * relu( np[b,i,h] + b1[h] + sum_e E[j,e]*W[e,h] )
__global__ __launch_bounds__(256, 2)
void edge_msg_tc(const float* __restrict__ edges,
                 const float* __restrict__ We,    // (64,256)
                 const float* __restrict__ b1,    // (256)
                 const float* __restrict__ np,    // (ROWS,256)
                 const int* __restrict__ mask,
                 float* __restrict__ s_out) {
    __shared__ __align__(16) unsigned sE[128 * 68];  // 34816 B, tf32 bits
    __shared__ float smj[NN];

    int row = blockIdx.x;              // b*N + i
    int b = row >> 7;
    int t = threadIdx.x;
    int w = t >> 5;
    int lane = t & 31;
    int hb = w * 32;
    int r = lane >> 2;                 // 0..7  (row group)
    int c = lane & 3;                  // 0..3  (col group)

    // ---- stage E tile (128 j-rows x 64 e) into smem, converting to tf32 ----
    const float4* src = (const float4*)(edges + (size_t)row * NN * EE);
#pragma unroll
    for (int g = t; g < 2048; g += 256) {   // 2048 float4
        float4 v = src[g];
        int rr = g >> 4, c4 = (g & 15) * 4;
        unsigned* d = &sE[rr * 68 + c4];
        d[0] = f2tf(v.x); d[1] = f2tf(v.y); d[2] = f2tf(v.z); d[3] = f2tf(v.w);
    }
    if (t < NN) smj[t] = mask[b*NN + t] ? 1.f : 0.f;

    // ---- preload B fragments: W[64,256] row-major(k,h) ----
    unsigned B0[4][8], B1[4][8];
#pragma unroll
    for (int nt = 0; nt < 4; nt++) {
        int col = hb + nt*8 + r;
#pragma unroll
        for (int k = 0; k < 8; k++) {
            B0[nt][k] = f2tf(We[(k*8 + c)     * HH + col]);
            B1[nt][k] = f2tf(We[(k*8 + c + 4) * HH + col]);
        }
    }

    // ---- npv = np + b1 for this lane's h columns ----
    float npv0[4], npv1[4];
#pragma unroll
    for (int nt = 0; nt < 4; nt++) {
        int h = hb + nt*8 + 2*c;
        npv0[nt] = np[(size_t)row*HH + h]     + b1[h];
        npv1[nt] = np[(size_t)row*HH + h + 1] + b1[h + 1];
    }

    float s0[4] = {0.f, 0.f, 0.f, 0.f};
    float s1[4] = {0.f, 0.f, 0.f, 0.f};

    __syncthreads();

    // ---- main loop: 8 m-tiles of 16 j-rows ----
#pragma unroll 1
    for (int m0 = 0; m0 < 8; m0++) {
        float acc[4][4];
#pragma unroll
        for (int nt = 0; nt < 4; nt++) {
            acc[nt][0] = 0.f; acc[nt][1] = 0.f; acc[nt][2] = 0.f; acc[nt][3] = 0.f;
        }
        int rbase0 = (m0*16 + r) * 68;
        int rbase1 = (m0*16 + r + 8) * 68;
#pragma unroll
        for (int k = 0; k < 8; k++) {
            unsigned a0 = sE[rbase0 + k*8 + c];
            unsigned a1 = sE[rbase1 + k*8 + c];
            unsigned a2 = sE[rbase0 + k*8 + c + 4];
            unsigned a3 = sE[rbase1 + k*8 + c + 4];
#pragma unroll
            for (int nt = 0; nt < 4; nt++)
                mma_tf32(acc[nt], a0, a1, a2, a3, B0[nt][k], B1[nt][k]);
        }
        float mj0 = smj[m0*16 + r];
        float mj1 = smj[m0*16 + r + 8];
#pragma unroll
        for (int nt = 0; nt < 4; nt++) {
            s0[nt] += mj0 * fmaxf(acc[nt][0] + npv0[nt], 0.f)
                    + mj1 * fmaxf(acc[nt][2] + npv0[nt], 0.f);
            s1[nt] += mj0 * fmaxf(acc[nt][1] + npv1[nt], 0.f)
                    + mj1 * fmaxf(acc[nt][3] + npv1[nt], 0.f);
        }
    }

    // ---- cross-lane reduce over row groups ----
#pragma unroll
    for (int off = 4; off < 32; off <<= 1) {
#pragma unroll
        for (int nt = 0; nt < 4; nt++) {
            s0[nt] += __shfl_xor_sync(0xffffffffu, s0[nt], off);
            s1[nt] += __shfl_xor_sync(0xffffffffu, s1[nt], off);
        }
    }

    float mi = mask[row] ? 1.f : 0.f;
    if (lane < 4) {
#pragma unroll
        for (int nt = 0; nt < 4; nt++) {
            int h = hb + nt*8 + 2*lane;
            s_out[(size_t)row*HH + h]     = mi * s0[nt];
            s_out[(size_t)row*HH + h + 1] = mi * s1[nt];
        }
    }
}

// ---------------- 3xTF32 split tensor-core GEMM, double-buffered ----------------
// C(M,N) = epilogue( [A | A2](M,K) @ W(K,N) ), near-fp32 accuracy via
// Ah*Bh + Al*Bh + Ah*Bl. Block tile 64x64, 128 threads (2x2 warps, warp 32x32),
// K-chunk 32. Requires M%64==0, N%64==0, K%32==0, K1%32==0.
__global__ __launch_bounds__(128)
void gemm_tc(int M, int N, int K, int K1,
             const float* __restrict__ A, int lda,
             const float* __restrict__ A2, int lda2,
             const float* __restrict__ W, int ldw,
             const float* __restrict__ bias,
             const float* __restrict__ rowscale,
             const int* __restrict__ maskrow,
             float* __restrict__ C, int ldc, int flags) {
    __shared__ __align__(16) float sA[2][64 * 36];   // raw fp32, stride 36
    __shared__ __align__(16) float sB[2][32 * 72];   // raw fp32, stride 72

    int tid = threadIdx.x;
    int w = tid >> 5;
    int lane = tid & 31;
    int wm = w & 1, wn = w >> 1;       // 2x2 warp grid
    int r = lane >> 2, c = lane & 3;

    int bm = blockIdx.y * 64, bn = blockIdx.x * 64;

    float acc[2][4][4];
#pragma unroll
    for (int mt = 0; mt < 2; mt++)
#pragma unroll
        for (int nt = 0; nt < 4; nt++)
#pragma unroll
            for (int i = 0; i < 4; i++) acc[mt][nt][i] = 0.f;

    float4 pa[4], pb[4];

    // prefetch helper (manually inlined twice below)
#define PREFETCH(k0_) do {                                                   \
    _Pragma("unroll")                                                        \
    for (int q = 0; q < 4; q++) {                                            \
        int g = tid + q*128;                                                 \
        int row_ = g >> 3, col4 = (g & 7) * 4;                               \
        int gm = bm + row_, gk = (k0_) + col4;                               \
        if (A2 != nullptr && gk >= K1)                                       \
            pa[q] = *(const float4*)(A2 + (size_t)gm*lda2 + (gk - K1));      \
        else                                                                 \
            pa[q] = *(const float4*)(A + (size_t)gm*lda + gk);               \
    }                                                                        \
    _Pragma("unroll")                                                        \
    for (int q = 0; q < 4; q++) {                                            \
        int g = tid + q*128;                                                 \
        int row_ = g >> 4, col4 = (g & 15) * 4;                              \
        pb[q] = *(const float4*)(W + (size_t)((k0_) + row_)*ldw + bn + col4);\
    }                                                                        \
} while (0)

#define STORE_STAGE(s_) do {                                                 \
    _Pragma("unroll")                                                        \
    for (int q = 0; q < 4; q++) {                                            \
        int g = tid + q*128;                                                 \
        int row_ = g >> 3, col4 = (g & 7) * 4;                               \
        *(float4*)&sA[s_][row_*36 + col4] = pa[q];                           \
    }                                                                        \
    _Pragma("unroll")                                                        \
    for (int q = 0; q < 4; q++) {                                            \
        int g = tid + q*128;                                                 \
        int row_ = g >> 4, col4 = (g & 15) * 4;                              \
        *(float4*)&sB[s_][row_*72 + col4] = pb[q];                           \
    }                                                                        \
} while (0)

    PREFETCH(0);
    STORE_STAGE(0);
    __syncthreads();

    int s = 0;
    for (int k0 = 0; ; ) {
        bool haveNext = (k0 + 32 < K);
        if (haveNext) PREFETCH(k0 + 32);

        // compute on buffer s
#pragma unroll
        for (int kk = 0; kk < 4; kk++) {
            unsigned bh0[4], bl0[4], bh1[4], bl1[4];
#pragma unroll
            for (int nt = 0; nt < 4; nt++) {
                int col = wn*32 + nt*8 + r;
                tfsplit(sB[s][(kk*8 + c)     * 72 + col], bh0[nt], bl0[nt]);
                tfsplit(sB[s][(kk*8 + c + 4) * 72 + col], bh1[nt], bl1[nt]);
            }
#pragma unroll
            for (int mt = 0; mt < 2; mt++) {
                int row0 = (wm*32 + mt*16 + r) * 36;
                int row1 = (wm*32 + mt*16 + r + 8) * 36;
                unsigned ah0, al0, ah1, al1, ah2, al2, ah3, al3;
                tfsplit(sA[s][row0 + kk*8 + c],     ah0, al0);
                tfsplit(sA[s][row1 + kk*8 + c],     ah1, al1);
                tfsplit(sA[s][row0 + kk*8 + c + 4], ah2, al2);
                tfsplit(sA[s][row1 + kk*8 + c + 4], ah3, al3);
#pragma unroll
                for (int nt = 0; nt < 4; nt++) {
                    mma_tf32(acc[mt][nt], ah0, ah1, ah2, ah3, bh0[nt], bh1[nt]);
                    mma_tf32(acc[mt][nt], al0, al1, al2, al3, bh0[nt], bh1[nt]);
                    mma_tf32(acc[mt][nt], ah0, ah1, ah2, ah3, bl0[nt], bl1[nt]);
                }
            }
        }

        k0 += 32;
        if (!haveNext) break;
        STORE_STAGE(s ^ 1);       // other buffer: no race with readers of s
        __syncthreads();
        s ^= 1;
    }
#undef PREFETCH
#undef STORE_STAGE

    // epilogue
#pragma unroll
    for (int mt = 0; mt < 2; mt++) {
#pragma unroll
        for (int i2 = 0; i2 < 2; i2++) {      // row sub (r / r+8)
            int gm = bm + wm*32 + mt*16 + r + i2*8;
            float rs = (rowscale != nullptr) ? rowscale[gm] : 1.f;
            float mf = (flags & GMASK) ? (maskrow[gm] ? 1.f : 0.f) : 1.f;
#pragma unroll
            for (int nt = 0; nt < 4; nt++) {
#pragma unroll
                for (int j = 0; j < 2; j++) {
                    int gn = bn + wn*32 + nt*8 + 2*c + j;
                    float v = acc[mt][nt][i2*2 + j];
                    if (bias != nullptr) v += bias[gn] * rs;
                    if (flags & GRELU) v = fmaxf(v, 0.f);
                    v *= mf;
                    C[(size_t)gm*ldc + gn] = v;
                }
            }
        }
    }
}

// ---------------- fused residual + LayerNorm: x = LN(x + u*mi)*g + b, then *mi ----
__global__ void ln_kernel(const float* __restrict__ u,
                          const int* __restrict__ mask,
                          const float* __restrict__ gw,
                          const float* __restrict__ bw,
                          float* __restrict__ x) {
    int warp = threadIdx.x >> 5;
    int lane = threadIdx.x & 31;
    int row = blockIdx.x * 8 + warp;
    float mi = mask[row] ? 1.f : 0.f;

    float v[4];
#pragma unroll
    for (int q = 0; q < 4; q++) {
        int d = lane + q*32;
        v[q] = x[(size_t)row*DD + d] + u[(size_t)row*DD + d] * mi;
    }
    float s = v[0] + v[1] + v[2] + v[3];
#pragma unroll
    for (int o = 16; o > 0; o >>= 1) s += __shfl_xor_sync(0xffffffffu, s, o);
    float mu = s * (1.f / DD);
    float var = 0.f;
#pragma unroll
    for (int q = 0; q < 4; q++) { float d2 = v[q] - mu; var += d2*d2; }
#pragma unroll
    for (int o = 16; o > 0; o >>= 1) var += __shfl_xor_sync(0xffffffffu, var, o);
    float rstd = rsqrtf(var * (1.f / DD) + EPSLN);
#pragma unroll
    for (int q = 0; q < 4; q++) {
        int d = lane + q*32;
        x[(size_t)row*DD + d] = ((v[q] - mu) * rstd * gw[d] + bw[d]) * mi;
    }
}

// ---------------- host launch ----------------
extern "C" void kernel_launch(void* const* d_in, const int* in_sizes, int n_in,
                              void* d_out, int out_size) {
    const float* nodes  = (const float*)d_in[0];
    const float* edges  = (const float*)d_in[1];
    const int*   mask   = (const int*)d_in[2];
    const float* msg_w1 = (const float*)d_in[3];   // (L,192,256)
    const float* msg_b1 = (const float*)d_in[4];   // (L,256)
    const float* msg_w2 = (const float*)d_in[5];   // (L,256,256)
    const float* msg_b2 = (const float*)d_in[6];   // (L,256)
    const float* upd_w1 = (const float*)d_in[7];   // (L,384,256)
    const float* upd_b1 = (const float*)d_in[8];   // (L,256)
    const float* upd_w2 = (const float*)d_in[9];   // (L,256,128)
    const float* upd_b2 = (const float*)d_in[10];  // (L,128)
    const float* ln_g   = (const float*)d_in[11];  // (L,128)
    const float* ln_b   = (const float*)d_in[12];  // (L,128)
    const float* out_w1 = (const float*)d_in[13];  // (128,256)
    const float* out_b1 = (const float*)d_in[14];  // (256)
    const float* out_w2 = (const float*)d_in[15];  // (256,128)
    const float* out_b2 = (const float*)d_in[16];  // (128)
    float* out = (float*)d_out;

    float *x, *np, *s, *agg, *u1, *u, *cnt;
    cudaGetSymbolAddress((void**)&x,   g_x);
    cudaGetSymbolAddress((void**)&np,  g_np);
    cudaGetSymbolAddress((void**)&s,   g_s);
    cudaGetSymbolAddress((void**)&agg, g_agg);
    cudaGetSymbolAddress((void**)&u1,  g_u1);
    cudaGetSymbolAddress((void**)&u,   g_u);
    cudaGetSymbolAddress((void**)&cnt, g_cnt);

    prep_x_kernel<<<ROWS, DD>>>(nodes, mask, x);
    prep_cnt_kernel<<<BATCH, NN>>>(mask, cnt);

    for (int l = 0; l < 3; l++) {
        const float* w1n = msg_w1 + (size_t)l * 192 * HH;          // node part rows 0..127
        const float* w1e = w1n + (size_t)DD * HH;                  // edge part rows 128..191
        const float* b1  = msg_b1 + (size_t)l * HH;
        const float* w2  = msg_w2 + (size_t)l * HH * HH;
        const float* b2  = msg_b2 + (size_t)l * HH;
        const float* uw1 = upd_w1 + (size_t)l * 384 * HH;
        const float* ub1 = upd_b1 + (size_t)l * HH;
        const float* uw2 = upd_w2 + (size_t)l * HH * DD;
        const float* ub2 = upd_b2 + (size_t)l * DD;
        const float* lg  = ln_g + (size_t)l * DD;
        const float* lb  = ln_b + (size_t)l * DD;

        // np = x @ w1n      (2048,256,K=128)
        gemm_tc<<<dim3(HH/64, ROWS/64), 128>>>(ROWS, HH, DD, 0,
            x, DD, nullptr, 0, w1n, HH, nullptr, nullptr, nullptr, np, HH, 0);

        // s = masked relu-reduce of (np + edges@w1e + b1)   [tf32 tensor cores]
        edge_msg_tc<<<ROWS, 256>>>(edges, w1e, b1, np, mask, s);

        // agg = s @ w2 + cnt*b2   (2048,256,K=256)
        gemm_tc<<<dim3(HH/64, ROWS/64), 128>>>(ROWS, HH, HH, 0,
            s, HH, nullptr, 0, w2, HH, b2, cnt, nullptr, agg, HH, 0);

        // u1 = relu([x,agg] @ uw1 + ub1)   (2048,256,K=384, split at 128)
        gemm_tc<<<dim3(HH/64, ROWS/64), 128>>>(ROWS, HH, DD + HH, DD,
            x, DD, agg, HH, uw1, HH, ub1, nullptr, nullptr, u1, HH, GRELU);

        // u = u1 @ uw2 + ub2   (2048,128,K=256)
        gemm_tc<<<dim3(DD/64, ROWS/64), 128>>>(ROWS, DD, HH, 0,
            u1, HH, nullptr, 0, uw2, DD, ub2, nullptr, nullptr, u, DD, 0);

        // x = LN(x + u*mi)*mi
        ln_kernel<<<ROWS/8, 256>>>(u, mask, lg, lb, x);
    }

    // z = relu(x @ out_w1 + out_b1)  -> reuse u1
    gemm_tc<<<dim3(HH/64, ROWS/64), 128>>>(ROWS, HH, DD, 0,
        x, DD, nullptr, 0, out_w1, HH, out_b1, nullptr, nullptr, u1, HH, GRELU);

    // out = (z @ out_w2 + out_b2) * mask
    gemm_tc<<<dim3(DD/64, ROWS/64), 128>>>(ROWS, DD, HH, 0,
        u1, HH, nullptr, 0, out_w2, DD, out_b2, nullptr, mask, out, DD, GMASK);
}